// round 1
// baseline (speedup 1.0000x reference)
#include <cuda_runtime.h>
#include <cstdint>

#define M_GT 128
#define MAX_N 262144
#define NBLOCKS_B 444
#define TPB 256

// Scratch (allocation-free: __device__ globals)
__device__ float g_maxiou[MAX_N];
__device__ int   g_argmax[MAX_N];
__device__ unsigned long long g_part[M_GT * NBLOCKS_B]; // per-(gt, block) packed best
__device__ unsigned g_forced[M_GT];                     // winning anchor idx per gt

// -------------------- Kernel B: IoU + per-anchor max/argmax + per-gt block best --------------------
__global__ __launch_bounds__(TPB) void iou_kernel(const float4* __restrict__ anchors,
                                                  const float4* __restrict__ gtb,
                                                  int N) {
    __shared__ float4 s_gt[M_GT];
    __shared__ float  s_area[M_GT];
    __shared__ unsigned long long s_best[M_GT];

    const int t = threadIdx.x;
    if (t < M_GT) {
        float4 g = gtb[t];
        s_gt[t] = g;
        s_area[t] = (g.z - g.x) * (g.w - g.y);
        s_best[t] = 0x00000000FFFFFFFFull;  // iou=0, idx=~0xFFFFFFFF=0 (matches argmax of all-zero column)
    }
    __syncthreads();

    const int lane = t & 31;

    for (int base = blockIdx.x * TPB; base < N; base += TPB * NBLOCKS_B) {
        const int i = base + t;               // block-uniform loop => all 32 lanes active in redux
        const bool valid = (i < N);
        const int ic = valid ? i : (N - 1);

        float4 a = anchors[ic];
        float area_a = (a.z - a.x) * (a.w - a.y);

        float best_iou = -1.0f;  // first gt with iou 0 beats -1 -> argmax 0 when all zero
        int   best_j = 0;
        const unsigned ai = (unsigned)i;

        #pragma unroll 4
        for (int m = 0; m < M_GT; m++) {
            float4 g = s_gt[m];
            float lx = fmaxf(a.x, g.x);
            float ly = fmaxf(a.y, g.y);
            float rx = fminf(a.z, g.z);
            float ry = fminf(a.w, g.w);
            float w = fmaxf(rx - lx, 0.0f);
            float h = fmaxf(ry - ly, 0.0f);
            float inter = w * h;
            float uni = area_a + s_area[m] - inter;
            float iou = inter / uni;          // full-precision div: matches reference bitwise

            if (iou > best_iou) { best_iou = iou; best_j = m; }  // strictly-greater = first-max

            // per-gt argmax over anchors: warp redux, then lane0 -> shared packed atomicMax
            unsigned key = valid ? __float_as_uint(iou) : 0u;    // iou >= 0 -> bits monotonic
            unsigned wmax = __reduce_max_sync(0xFFFFFFFFu, key);
            if (wmax != 0u) {
                unsigned cand = (key == wmax) ? ai : 0xFFFFFFFFu;
                unsigned widx = __reduce_min_sync(0xFFFFFFFFu, cand);  // first index on tie
                if (lane == 0) {
                    unsigned long long p =
                        ((unsigned long long)wmax << 32) | (unsigned long long)(~widx);
                    atomicMax(&s_best[m], p);
                }
            }
        }
        if (valid) {
            g_maxiou[i] = best_iou;
            g_argmax[i] = best_j;
        }
    }
    __syncthreads();
    if (t < M_GT) g_part[(size_t)t * NBLOCKS_B + blockIdx.x] = s_best[t];
}

// -------------------- Kernel R: reduce per-block winners -> forced anchor per gt --------------------
__global__ void reduce_kernel() {
    const int m = blockIdx.x;       // 128 blocks, 32 threads
    const int lane = threadIdx.x;
    unsigned long long best = 0x00000000FFFFFFFFull;
    for (int b = lane; b < NBLOCKS_B; b += 32) {
        unsigned long long v = g_part[(size_t)m * NBLOCKS_B + b];
        if (v > best) best = v;
    }
    #pragma unroll
    for (int o = 16; o > 0; o >>= 1) {
        unsigned long long v = __shfl_down_sync(0xFFFFFFFFu, best, o);
        if (v > best) best = v;
    }
    if (lane == 0) g_forced[m] = ~(unsigned)(best & 0xFFFFFFFFull);
}

// -------------------- Kernel C: epilogue (masks, labels, box encode, outputs) --------------------
__global__ __launch_bounds__(TPB) void out_kernel(const float4* __restrict__ anchors,
                                                  const float4* __restrict__ gtb,
                                                  const int* __restrict__ labels,
                                                  float* __restrict__ out,
                                                  int N) {
    __shared__ unsigned s_force[M_GT];
    __shared__ float4   s_gt[M_GT];
    __shared__ int      s_lab[M_GT];

    const int t = threadIdx.x;
    if (t < M_GT) {
        s_force[t] = g_forced[t];
        s_gt[t]    = gtb[t];
        s_lab[t]   = labels[t];
    }
    __syncthreads();

    const int i = blockIdx.x * TPB + t;
    if (i >= N) return;

    const unsigned ui = (unsigned)i;
    bool forced = false;
    #pragma unroll
    for (int m = 0; m < M_GT; m++) forced |= (s_force[m] == ui);

    float maxiou = g_maxiou[i];
    int   j      = g_argmax[i];

    bool pos = (maxiou >= 0.5f) || forced;
    bool neg = (maxiou < 0.4f) && !pos;
    int  cls = pos ? s_lab[j] : (neg ? 0 : -1);

    float4 a = anchors[i];
    float4 g = s_gt[j];

    const float eps = 1.19209290e-07f;  // FLT_EPSILON, matches jnp.finfo(float32).eps
    float ax = (a.x + a.z) * 0.5f;
    float ay = (a.y + a.w) * 0.5f;
    float aw = fmaxf(a.z - a.x, eps);
    float ah = fmaxf(a.w - a.y, eps);
    float gx = (g.x + g.z) * 0.5f;
    float gy = (g.y + g.w) * 0.5f;
    float gw = g.z - g.x;
    float gh = g.w - g.y;

    float dx = (gx - ax) / aw;
    float dy = (gy - ay) / ah;
    float dw = logf(gw / aw);
    float dh = logf(gh / ah);

    // output layout (float32): [cls (N)] [reg (N,4)] [pos (N)]
    out[i] = (float)cls;
    float4 r = pos ? make_float4(dx, dy, dw, dh) : make_float4(0.f, 0.f, 0.f, 0.f);
    reinterpret_cast<float4*>(out + N)[i] = r;   // out+N is 16B-aligned (N multiple of 4)
    out[5 * N + i] = pos ? 1.0f : 0.0f;
}

extern "C" void kernel_launch(void* const* d_in, const int* in_sizes, int n_in,
                              void* d_out, int out_size) {
    const float4* anchors = (const float4*)d_in[0];
    const float4* gtb     = (const float4*)d_in[1];
    const int*    labels  = (const int*)d_in[2];
    float* out = (float*)d_out;
    const int N = in_sizes[0] / 4;

    iou_kernel<<<NBLOCKS_B, TPB>>>(anchors, gtb, N);
    reduce_kernel<<<M_GT, 32>>>();
    out_kernel<<<(N + TPB - 1) / TPB, TPB>>>(anchors, gtb, labels, out, N);
}